// round 3
// baseline (speedup 1.0000x reference)
#include <cuda_runtime.h>
#include <cuda_bf16.h>
#include <mma.h>

using namespace nvcuda;

// ---------------- problem constants ----------------
#define C_DIM 512
#define HW    4096
#define BATCH 2
#define NGRP  32
#define CPG   16   // channels per group

// ---------------- scratch (device globals; no allocs allowed) ----------------
__device__ __nv_bfloat16 g_hn  [(size_t)BATCH * C_DIM * HW];      // groupnormed, bf16 [b,c,hw]
__device__ __nv_bfloat16 g_W   [4 * C_DIM * C_DIM];               // wq,wk,wv,wo in bf16
__device__ __nv_bfloat16 g_qT  [(size_t)BATCH * HW * C_DIM];      // q^T (scaled)  [b,hw,c]
__device__ __nv_bfloat16 g_k   [(size_t)BATCH * C_DIM * HW];      // k             [b,c,hw]
__device__ __nv_bfloat16 g_vT  [(size_t)BATCH * HW * C_DIM];      // v^T           [b,hw,c]
__device__ float         g_scores[(size_t)BATCH * HW * HW];       // fp32 scores   [b,hw,hw]
__device__ __nv_bfloat16 g_attn  [(size_t)BATCH * HW * HW];       // softmaxed, bf16
__device__ __nv_bfloat16 g_outT  [(size_t)BATCH * HW * C_DIM];    // (attn V)^T    [b,hw,c]

// ---------------- GroupNorm ----------------
__global__ void gn_kernel(const float* __restrict__ x,
                          const float* __restrict__ gamma,
                          const float* __restrict__ beta,
                          __nv_bfloat16* __restrict__ hn) {
    int b = blockIdx.x >> 5, g = blockIdx.x & 31;
    size_t base = ((size_t)b * C_DIM + g * CPG) * HW;   // 65536 floats per group
    const float4* xp = (const float4*)(x + base);
    int tid = threadIdx.x;

    float s = 0.f, s2 = 0.f;
    for (int v = tid; v < 16384; v += 256) {
        float4 t = xp[v];
        s  += t.x + t.y + t.z + t.w;
        s2 += t.x*t.x + t.y*t.y + t.z*t.z + t.w*t.w;
    }
    __shared__ float r1[256], r2[256];
    r1[tid] = s; r2[tid] = s2; __syncthreads();
    for (int st = 128; st > 0; st >>= 1) {
        if (tid < st) { r1[tid] += r1[tid+st]; r2[tid] += r2[tid+st]; }
        __syncthreads();
    }
    float mean = r1[0] * (1.0f/65536.0f);
    float var  = r2[0] * (1.0f/65536.0f) - mean*mean;
    float inv  = rsqrtf(var + 1e-6f);

    __nv_bfloat162* out2 = (__nv_bfloat162*)(hn + base);
    for (int v = tid; v < 16384; v += 256) {
        float4 t = xp[v];
        int c = g*CPG + (v >> 10);      // 1024 float4 per channel
        float ga = gamma[c] * inv;
        float be = beta[c] - mean * ga;
        out2[v*2]   = __floats2bfloat162_rn(t.x*ga+be, t.y*ga+be);
        out2[v*2+1] = __floats2bfloat162_rn(t.z*ga+be, t.w*ga+be);
    }
}

// ---------------- weight fp32 -> bf16 ----------------
__global__ void convw_kernel(const float* __restrict__ wq, const float* __restrict__ wk,
                             const float* __restrict__ wv, const float* __restrict__ wo,
                             __nv_bfloat16* __restrict__ W) {
    int i = blockIdx.x * blockDim.x + threadIdx.x;   // 0 .. 4*262144-1
    const float* src;
    int which = i >> 18, off = i & 262143;
    src = (which == 0) ? wq : (which == 1) ? wk : (which == 2) ? wv : wo;
    W[i] = __float2bfloat16(src[off]);
}

// ---------------- row softmax: fp32 scores -> bf16 attn ----------------
__global__ void softmax_kernel(const float* __restrict__ scores,
                               __nv_bfloat16* __restrict__ attn) {
    const int n = HW;
    size_t row = blockIdx.x;
    const float4* src = (const float4*)(scores + row * n);
    __shared__ float buf[HW];
    __shared__ float red[256];
    int tid = threadIdx.x;

    float m = -1e30f;
    for (int v = tid; v < n/4; v += 256) {
        float4 t = src[v];
        ((float4*)buf)[v] = t;
        m = fmaxf(m, fmaxf(fmaxf(t.x, t.y), fmaxf(t.z, t.w)));
    }
    red[tid] = m; __syncthreads();
    for (int st = 128; st > 0; st >>= 1) {
        if (tid < st) red[tid] = fmaxf(red[tid], red[tid+st]);
        __syncthreads();
    }
    m = red[0];
    __syncthreads();

    float s = 0.f;
    for (int i = tid; i < n; i += 256) {
        float e = __expf(buf[i] - m);
        buf[i] = e;
        s += e;
    }
    red[tid] = s; __syncthreads();
    for (int st = 128; st > 0; st >>= 1) {
        if (tid < st) red[tid] += red[tid+st];
        __syncthreads();
    }
    float inv = 1.0f / red[0];
    __nv_bfloat16* dst = attn + row * (size_t)n;
    for (int i = tid; i < n; i += 256) dst[i] = __float2bfloat16(buf[i] * inv);
}

// ---------------- generic bf16 wmma GEMM ----------------
// C[m,n] = (sum_k A[m,k] B[k,n] + bias[m]) * scale + resid[m,n]
// BCOL : B stored column-major (element (k,n) at n*ldb + k)
// OUTM : 0 = bf16 row-major, 1 = bf16 transposed (C[n*ldc+m]), 2 = fp32 row-major
#define BM 128
#define BN 128
#define BK 32

template<bool BCOL, int OUTM, bool BIAS, bool RESID>
__global__ void __launch_bounds__(256)
gemm_kernel(const __nv_bfloat16* __restrict__ A, const __nv_bfloat16* __restrict__ B,
            void* __restrict__ C, const float* __restrict__ bias,
            const float* __restrict__ resid,
            int M, int N, int K, int lda, int ldb, int ldc,
            long long strideA, long long strideB, long long strideC, long long strideR,
            float scale)
{
    __shared__ __align__(16) char smem_raw[64 * 132 * 4];     // 33792 B (C-union)
    __nv_bfloat16* sA = (__nv_bfloat16*)smem_raw;             // 128 x (32+8)
    __nv_bfloat16* sB = sA + 128 * 40;                        // row: 32x136 / col: 128x40
    float* sC = (float*)smem_raw;                             // 64 x 132 (after loop)

    int tid  = threadIdx.x;
    int warp = tid >> 5;
    int wm = warp >> 2, wn = warp & 3;            // 2 x 4 warp grid, 64x32 warp tile
    int m0 = blockIdx.y * BM, n0 = blockIdx.x * BN;
    int bz = blockIdx.z;

    const __nv_bfloat16* Ab = A + (size_t)bz * strideA;
    const __nv_bfloat16* Bb = B + (size_t)bz * strideB;

    wmma::fragment<wmma::accumulator, 16,16,16, float> acc[4][2];
    #pragma unroll
    for (int i = 0; i < 4; i++)
        #pragma unroll
        for (int j = 0; j < 2; j++) wmma::fill_fragment(acc[i][j], 0.0f);

    int ktiles = K / BK;
    for (int kt = 0; kt < ktiles; ++kt) {
        // ---- load A tile 128x32 (always row-major) ----
        const __nv_bfloat16* Ag = Ab + (size_t)m0 * lda + kt * BK;
        #pragma unroll
        for (int v = 0; v < 2; ++v) {
            int idx = v * 256 + tid;
            int r = idx >> 2, c8 = (idx & 3) << 3;
            *(uint4*)&sA[r * 40 + c8] = *(const uint4*)&Ag[(size_t)r * lda + c8];
        }
        // ---- load B tile ----
        if (!BCOL) {
            const __nv_bfloat16* Bg = Bb + (size_t)(kt * BK) * ldb + n0;
            #pragma unroll
            for (int v = 0; v < 2; ++v) {
                int idx = v * 256 + tid;
                int r = idx >> 4, c8 = (idx & 15) << 3;
                *(uint4*)&sB[r * 136 + c8] = *(const uint4*)&Bg[(size_t)r * ldb + c8];
            }
        } else {
            const __nv_bfloat16* Bg = Bb + (size_t)n0 * ldb + kt * BK;
            #pragma unroll
            for (int v = 0; v < 2; ++v) {
                int idx = v * 256 + tid;
                int r = idx >> 2, c8 = (idx & 3) << 3;   // r = local n, c8 = k offset
                *(uint4*)&sB[r * 40 + c8] = *(const uint4*)&Bg[(size_t)r * ldb + c8];
            }
        }
        __syncthreads();

        #pragma unroll
        for (int kk = 0; kk < 2; ++kk) {
            wmma::fragment<wmma::matrix_a, 16,16,16, __nv_bfloat16, wmma::row_major> af[4];
            #pragma unroll
            for (int i = 0; i < 4; i++)
                wmma::load_matrix_sync(af[i], &sA[(wm*64 + i*16) * 40 + kk*16], 40);
            #pragma unroll
            for (int j = 0; j < 2; j++) {
                if (!BCOL) {
                    wmma::fragment<wmma::matrix_b, 16,16,16, __nv_bfloat16, wmma::row_major> bf;
                    wmma::load_matrix_sync(bf, &sB[(kk*16) * 136 + wn*32 + j*16], 136);
                    #pragma unroll
                    for (int i = 0; i < 4; i++) wmma::mma_sync(acc[i][j], af[i], bf, acc[i][j]);
                } else {
                    wmma::fragment<wmma::matrix_b, 16,16,16, __nv_bfloat16, wmma::col_major> bf;
                    wmma::load_matrix_sync(bf, &sB[(wn*32 + j*16) * 40 + kk*16], 40);
                    #pragma unroll
                    for (int i = 0; i < 4; i++) wmma::mma_sync(acc[i][j], af[i], bf, acc[i][j]);
                }
            }
        }
        __syncthreads();
    }

    // ---- epilogue: two 64-row chunks staged through smem ----
    #pragma unroll
    for (int chunk = 0; chunk < 2; ++chunk) {
        __syncthreads();
        if (wm == chunk) {
            #pragma unroll
            for (int i = 0; i < 4; i++)
                #pragma unroll
                for (int j = 0; j < 2; j++)
                    wmma::store_matrix_sync(&sC[(i*16) * 132 + wn*32 + j*16],
                                            acc[i][j], 132, wmma::mem_row_major);
        }
        __syncthreads();

        if (OUTM == 1) {
            // transposed store: make gm the fast index for coalescing
            for (int idx = tid; idx < 64 * 128; idx += 256) {
                int r = idx & 63, cn = idx >> 6;
                int gm = m0 + chunk * 64 + r, gn = n0 + cn;
                float v = sC[r * 132 + cn];
                if (BIAS) v += bias[gm];
                v *= scale;
                ((__nv_bfloat16*)C)[(size_t)bz*strideC + (size_t)gn*ldc + gm] = __float2bfloat16(v);
            }
        } else {
            for (int idx = tid; idx < 64 * 128; idx += 256) {
                int r = idx >> 7, cn = idx & 127;
                int gm = m0 + chunk * 64 + r, gn = n0 + cn;
                float v = sC[r * 132 + cn];
                if (BIAS) v += bias[gm];
                v *= scale;
                if (RESID) v += resid[(size_t)bz*strideR + (size_t)gm*N + gn];
                if (OUTM == 0)
                    ((__nv_bfloat16*)C)[(size_t)bz*strideC + (size_t)gm*ldc + gn] = __float2bfloat16(v);
                else
                    ((float*)C)[(size_t)bz*strideC + (size_t)gm*ldc + gn] = v;
            }
        }
    }
}

// ---------------- launch ----------------
extern "C" void kernel_launch(void* const* d_in, const int* in_sizes, int n_in,
                              void* d_out, int out_size) {
    (void)in_sizes; (void)n_in; (void)out_size;
    const float* x     = (const float*)d_in[0];
    const float* gamma = (const float*)d_in[1];
    const float* beta  = (const float*)d_in[2];
    const float* wq    = (const float*)d_in[3];
    const float* bq    = (const float*)d_in[4];
    const float* wk    = (const float*)d_in[5];
    const float* bk    = (const float*)d_in[6];
    const float* wv    = (const float*)d_in[7];
    const float* bv    = (const float*)d_in[8];
    const float* wo    = (const float*)d_in[9];
    const float* bo    = (const float*)d_in[10];
    float* out = (float*)d_out;

    __nv_bfloat16 *hn, *W, *qT, *kb, *vT, *attn, *outT;
    float* scores;
    cudaGetSymbolAddress((void**)&hn,     g_hn);
    cudaGetSymbolAddress((void**)&W,      g_W);
    cudaGetSymbolAddress((void**)&qT,     g_qT);
    cudaGetSymbolAddress((void**)&kb,     g_k);
    cudaGetSymbolAddress((void**)&vT,     g_vT);
    cudaGetSymbolAddress((void**)&scores, g_scores);
    cudaGetSymbolAddress((void**)&attn,   g_attn);
    cudaGetSymbolAddress((void**)&outT,   g_outT);

    gn_kernel<<<BATCH * NGRP, 256>>>(x, gamma, beta, hn);
    convw_kernel<<<4 * C_DIM * C_DIM / 256, 256>>>(wq, wk, wv, wo, W);

    const long long sHN = (long long)C_DIM * HW;   // 512*4096
    const long long sT  = (long long)HW * C_DIM;   // 4096*512
    const long long sSC = (long long)HW * HW;      // 4096*4096
    const float qscale = 0.044194173824159216f;    // 512^-0.5

    dim3 gProj(HW / BN, C_DIM / BM, BATCH);        // (32,4,2)
    // q^T = ((Wq hn + bq) * scale)^T   -> [b, hw, c]
    gemm_kernel<false,1,true,false><<<gProj,256>>>(W,               hn, qT, bq, nullptr,
        C_DIM, HW, C_DIM, C_DIM, HW, C_DIM, 0, sHN, sT, 0, qscale);
    // k = Wk hn + bk                    -> [b, c, hw]
    gemm_kernel<false,0,true,false><<<gProj,256>>>(W + 262144,      hn, kb, bk, nullptr,
        C_DIM, HW, C_DIM, C_DIM, HW, HW,    0, sHN, sHN, 0, 1.0f);
    // v^T = (Wv hn + bv)^T              -> [b, hw, c]
    gemm_kernel<false,1,true,false><<<gProj,256>>>(W + 2*262144,    hn, vT, bv, nullptr,
        C_DIM, HW, C_DIM, C_DIM, HW, C_DIM, 0, sHN, sT, 0, 1.0f);

    // scores[i,j] = qT[i,:] . k[:,j]   (scale already folded into q)
    dim3 gScores(HW / BN, HW / BM, BATCH);         // (32,32,2)
    gemm_kernel<false,2,false,false><<<gScores,256>>>(qT, kb, scores, nullptr, nullptr,
        HW, HW, C_DIM, C_DIM, HW, HW, sT, sHN, sSC, 0, 1.0f);

    softmax_kernel<<<BATCH * HW, 256>>>(scores, attn);

    // outT[i,c] = attn[i,:] . vT[:,c]
    dim3 gOut(C_DIM / BN, HW / BM, BATCH);         // (4,32,2)
    gemm_kernel<false,0,false,false><<<gOut,256>>>(attn, vT, outT, nullptr, nullptr,
        HW, C_DIM, HW, HW, C_DIM, C_DIM, sSC, sT, sT, 0, 1.0f);

    // y = x + Wo out + bo   (out[i,p] = outT[p,i] -> B col-major, ldb = 512)
    gemm_kernel<true,2,true,true><<<gProj,256>>>(W + 3*262144, outT, out, bo, x,
        C_DIM, HW, C_DIM, C_DIM, C_DIM, HW, 0, sT, sHN, sHN, 1.0f);
}

// round 5
// speedup vs baseline: 1.0891x; 1.0891x over previous
#include <cuda_runtime.h>
#include <cuda_bf16.h>
#include <mma.h>
#include <cstdint>
#include <cstddef>

using namespace nvcuda;

// ---------------- problem constants ----------------
#define C_DIM 512
#define HW    4096
#define BATCH 2
#define NGRP  32
#define CPG   16   // channels per group

// ---------------- scratch (device globals; no allocs allowed) ----------------
__device__ __nv_bfloat16 g_hn  [(size_t)BATCH * C_DIM * HW];      // groupnormed, bf16 [b,c,hw]
__device__ __nv_bfloat16 g_W   [4 * C_DIM * C_DIM];               // wq,wk,wv,wo in bf16
__device__ __nv_bfloat16 g_qT  [(size_t)BATCH * HW * C_DIM];      // q^T (scaled)  [b,hw,c]
__device__ __nv_bfloat16 g_k   [(size_t)BATCH * C_DIM * HW];      // k             [b,c,hw]
__device__ __nv_bfloat16 g_vT  [(size_t)BATCH * HW * C_DIM];      // v^T           [b,hw,c]
__device__ float         g_scores[(size_t)BATCH * HW * HW];       // fp32 scores   [b,hw,hw]
__device__ __nv_bfloat16 g_attn  [(size_t)BATCH * HW * HW];       // softmaxed, bf16
__device__ __nv_bfloat16 g_outT  [(size_t)BATCH * HW * C_DIM];    // (attn V)^T    [b,hw,c]

// ---------------- GroupNorm ----------------
__global__ void gn_kernel(const float* __restrict__ x,
                          const float* __restrict__ gamma,
                          const float* __restrict__ beta,
                          __nv_bfloat16* __restrict__ hn) {
    int b = blockIdx.x >> 5, g = blockIdx.x & 31;
    size_t base = ((size_t)b * C_DIM + g * CPG) * HW;   // 65536 floats per group
    const float4* xp = (const float4*)(x + base);
    int tid = threadIdx.x;

    float s = 0.f, s2 = 0.f;
    for (int v = tid; v < 16384; v += 256) {
        float4 t = xp[v];
        s  += t.x + t.y + t.z + t.w;
        s2 += t.x*t.x + t.y*t.y + t.z*t.z + t.w*t.w;
    }
    __shared__ float r1[256], r2[256];
    r1[tid] = s; r2[tid] = s2; __syncthreads();
    for (int st = 128; st > 0; st >>= 1) {
        if (tid < st) { r1[tid] += r1[tid+st]; r2[tid] += r2[tid+st]; }
        __syncthreads();
    }
    float mean = r1[0] * (1.0f/65536.0f);
    float var  = r2[0] * (1.0f/65536.0f) - mean*mean;
    float inv  = rsqrtf(var + 1e-6f);

    __nv_bfloat162* out2 = (__nv_bfloat162*)(hn + base);
    for (int v = tid; v < 16384; v += 256) {
        float4 t = xp[v];
        int c = g*CPG + (v >> 10);      // 1024 float4 per channel
        float ga = gamma[c] * inv;
        float be = beta[c] - mean * ga;
        out2[v*2]   = __floats2bfloat162_rn(t.x*ga+be, t.y*ga+be);
        out2[v*2+1] = __floats2bfloat162_rn(t.z*ga+be, t.w*ga+be);
    }
}

// ---------------- weight fp32 -> bf16 ----------------
__global__ void convw_kernel(const float* __restrict__ wq, const float* __restrict__ wk,
                             const float* __restrict__ wv, const float* __restrict__ wo,
                             __nv_bfloat16* __restrict__ W) {
    int i = blockIdx.x * blockDim.x + threadIdx.x;   // 0 .. 4*262144-1
    const float* src;
    int which = i >> 18, off = i & 262143;
    src = (which == 0) ? wq : (which == 1) ? wk : (which == 2) ? wv : wo;
    W[i] = __float2bfloat16(src[off]);
}

// ---------------- row softmax: fp32 scores -> bf16 attn ----------------
__global__ void softmax_kernel(const float* __restrict__ scores,
                               __nv_bfloat16* __restrict__ attn) {
    const int n = HW;
    size_t row = blockIdx.x;
    const float4* src = (const float4*)(scores + row * n);
    __shared__ float buf[HW];
    __shared__ float red[256];
    int tid = threadIdx.x;

    float m = -1e30f;
    for (int v = tid; v < n/4; v += 256) {
        float4 t = src[v];
        ((float4*)buf)[v] = t;
        m = fmaxf(m, fmaxf(fmaxf(t.x, t.y), fmaxf(t.z, t.w)));
    }
    red[tid] = m; __syncthreads();
    for (int st = 128; st > 0; st >>= 1) {
        if (tid < st) red[tid] = fmaxf(red[tid], red[tid+st]);
        __syncthreads();
    }
    m = red[0];
    __syncthreads();

    float s = 0.f;
    for (int i = tid; i < n; i += 256) {
        float e = __expf(buf[i] - m);
        buf[i] = e;
        s += e;
    }
    red[tid] = s; __syncthreads();
    for (int st = 128; st > 0; st >>= 1) {
        if (tid < st) red[tid] += red[tid+st];
        __syncthreads();
    }
    float inv = 1.0f / red[0];
    __nv_bfloat16* dst = attn + row * (size_t)n;
    for (int i = tid; i < n; i += 256) dst[i] = __float2bfloat16(buf[i] * inv);
}

// ---------------- cp.async helpers ----------------
__device__ __forceinline__ void cps16(uint32_t dst, const void* src) {
    asm volatile("cp.async.cg.shared.global [%0], [%1], 16;" :: "r"(dst), "l"(src));
}
__device__ __forceinline__ void cp_commit() {
    asm volatile("cp.async.commit_group;" ::: "memory");
}

// ---------------- generic bf16 wmma GEMM, 4-stage cp.async pipeline --------
// C[m,n] = (sum_k A[m,k] B[k,n] + bias[m]) * scale + resid[m,n]
// BCOL : B stored column-major (element (k,n) at n*ldb + k)
// OUTM : 0 = bf16 row-major, 1 = bf16 transposed (C[n*ldc+m]), 2 = fp32 row-major
#define BM 128
#define BN 128
#define BK 32
#define STAGES 4
#define A_ELEMS (128 * 40)          // 5120 bf16 per stage (pad 8)
#define B_ELEMS 5120                // max(32*136, 128*40)
#define STAGE_ELEMS (A_ELEMS + B_ELEMS)     // 10240 bf16 = 20480 B
#define SMEM_BYTES (STAGES * STAGE_ELEMS * 2)   // 81920 B

template<bool BCOL>
__device__ __forceinline__ void load_tile(
    const __nv_bfloat16* __restrict__ Ab, const __nv_bfloat16* __restrict__ Bb,
    int m0, int n0, int kt, int lda, int ldb, int tid,
    uint32_t sA_u32, uint32_t sB_u32)
{
    const __nv_bfloat16* Ag = Ab + (size_t)m0 * lda + kt * BK;
    #pragma unroll
    for (int v = 0; v < 2; ++v) {
        int idx = v * 256 + tid;
        int r = idx >> 2, c8 = (idx & 3) << 3;
        cps16(sA_u32 + (uint32_t)(r * 40 + c8) * 2, Ag + (size_t)r * lda + c8);
    }
    if (!BCOL) {
        const __nv_bfloat16* Bg = Bb + (size_t)(kt * BK) * ldb + n0;
        #pragma unroll
        for (int v = 0; v < 2; ++v) {
            int idx = v * 256 + tid;
            int r = idx >> 4, c8 = (idx & 15) << 3;
            cps16(sB_u32 + (uint32_t)(r * 136 + c8) * 2, Bg + (size_t)r * ldb + c8);
        }
    } else {
        const __nv_bfloat16* Bg = Bb + (size_t)n0 * ldb + kt * BK;
        #pragma unroll
        for (int v = 0; v < 2; ++v) {
            int idx = v * 256 + tid;
            int r = idx >> 2, c8 = (idx & 3) << 3;
            cps16(sB_u32 + (uint32_t)(r * 40 + c8) * 2, Bg + (size_t)r * ldb + c8);
        }
    }
}

template<bool BCOL, int OUTM, bool BIAS, bool RESID>
__global__ void __launch_bounds__(256)
gemm_kernel(const __nv_bfloat16* __restrict__ A, const __nv_bfloat16* __restrict__ B,
            void* __restrict__ C, const float* __restrict__ bias,
            const float* __restrict__ resid,
            int M, int N, int K, int lda, int ldb, int ldc,
            long long strideA, long long strideB, long long strideC, long long strideR,
            float scale)
{
    extern __shared__ __align__(16) char dsmem[];
    __nv_bfloat16* sbase = (__nv_bfloat16*)dsmem;
    float* sC = (float*)dsmem;                    // epilogue reuse: 64 x 132 fp32

    int tid  = threadIdx.x;
    int warp = tid >> 5;
    int wm = warp >> 2, wn = warp & 3;            // 2 x 4 warp grid, 64x32 warp tile
    int m0 = blockIdx.y * BM, n0 = blockIdx.x * BN;
    int bz = blockIdx.z;

    const __nv_bfloat16* Ab = A + (size_t)bz * strideA;
    const __nv_bfloat16* Bb = B + (size_t)bz * strideB;

    uint32_t smem_u32 = (uint32_t)__cvta_generic_to_shared(sbase);

    wmma::fragment<wmma::accumulator, 16,16,16, float> acc[4][2];
    #pragma unroll
    for (int i = 0; i < 4; i++)
        #pragma unroll
        for (int j = 0; j < 2; j++) wmma::fill_fragment(acc[i][j], 0.0f);

    int ktiles = K / BK;

    // ---- prologue: prefetch STAGES-1 tiles ----
    #pragma unroll
    for (int s = 0; s < STAGES - 1; ++s) {
        uint32_t sa = smem_u32 + (uint32_t)(s * STAGE_ELEMS) * 2;
        load_tile<BCOL>(Ab, Bb, m0, n0, s, lda, ldb, tid, sa, sa + A_ELEMS * 2);
        cp_commit();
    }

    for (int kt = 0; kt < ktiles; ++kt) {
        // wait until stage kt's group is complete (tail-exact counts)
        int rem = ktiles - 1 - kt;
        if (rem >= 2)      asm volatile("cp.async.wait_group 2;" ::: "memory");
        else if (rem == 1) asm volatile("cp.async.wait_group 1;" ::: "memory");
        else               asm volatile("cp.async.wait_group 0;" ::: "memory");
        __syncthreads();   // all warps done with stage (kt-1) compute + see stage kt

        // issue stage kt+STAGES-1 (overwrites stage kt-1, safe after sync)
        int nk = kt + STAGES - 1;
        if (nk < ktiles) {
            int s = nk % STAGES;
            uint32_t sa = smem_u32 + (uint32_t)(s * STAGE_ELEMS) * 2;
            load_tile<BCOL>(Ab, Bb, m0, n0, nk, lda, ldb, tid, sa, sa + A_ELEMS * 2);
            cp_commit();
        }

        // ---- compute stage kt ----
        __nv_bfloat16* sA = sbase + (kt % STAGES) * STAGE_ELEMS;
        __nv_bfloat16* sB = sA + A_ELEMS;

        #pragma unroll
        for (int kk = 0; kk < 2; ++kk) {
            wmma::fragment<wmma::matrix_a, 16,16,16, __nv_bfloat16, wmma::row_major> af[4];
            #pragma unroll
            for (int i = 0; i < 4; i++)
                wmma::load_matrix_sync(af[i], &sA[(wm*64 + i*16) * 40 + kk*16], 40);
            #pragma unroll
            for (int j = 0; j < 2; j++) {
                if (!BCOL) {
                    wmma::fragment<wmma::matrix_b, 16,16,16, __nv_bfloat16, wmma::row_major> bf;
                    wmma::load_matrix_sync(bf, &sB[(kk*16) * 136 + wn*32 + j*16], 136);
                    #pragma unroll
                    for (int i = 0; i < 4; i++) wmma::mma_sync(acc[i][j], af[i], bf, acc[i][j]);
                } else {
                    wmma::fragment<wmma::matrix_b, 16,16,16, __nv_bfloat16, wmma::col_major> bf;
                    wmma::load_matrix_sync(bf, &sB[(wn*32 + j*16) * 40 + kk*16], 40);
                    #pragma unroll
                    for (int i = 0; i < 4; i++) wmma::mma_sync(acc[i][j], af[i], bf, acc[i][j]);
                }
            }
        }
    }

    // ---- epilogue: two 64-row chunks staged through smem ----
    #pragma unroll
    for (int chunk = 0; chunk < 2; ++chunk) {
        __syncthreads();
        if (wm == chunk) {
            #pragma unroll
            for (int i = 0; i < 4; i++)
                #pragma unroll
                for (int j = 0; j < 2; j++)
                    wmma::store_matrix_sync(&sC[(i*16) * 132 + wn*32 + j*16],
                                            acc[i][j], 132, wmma::mem_row_major);
        }
        __syncthreads();

        if (OUTM == 1) {
            // transposed store: make gm the fast index for coalescing
            for (int idx = tid; idx < 64 * 128; idx += 256) {
                int r = idx & 63, cn = idx >> 6;
                int gm = m0 + chunk * 64 + r, gn = n0 + cn;
                float v = sC[r * 132 + cn];
                if (BIAS) v += bias[gm];
                v *= scale;
                ((__nv_bfloat16*)C)[(size_t)bz*strideC + (size_t)gn*ldc + gm] = __float2bfloat16(v);
            }
        } else {
            for (int idx = tid; idx < 64 * 128; idx += 256) {
                int r = idx >> 7, cn = idx & 127;
                int gm = m0 + chunk * 64 + r, gn = n0 + cn;
                float v = sC[r * 132 + cn];
                if (BIAS) v += bias[gm];
                v *= scale;
                if (RESID) v += resid[(size_t)bz*strideR + (size_t)gm*N + gn];
                if (OUTM == 0)
                    ((__nv_bfloat16*)C)[(size_t)bz*strideC + (size_t)gm*ldc + gn] = __float2bfloat16(v);
                else
                    ((float*)C)[(size_t)bz*strideC + (size_t)gm*ldc + gn] = v;
            }
        }
    }
}

// ---------------- launch ----------------
extern "C" void kernel_launch(void* const* d_in, const int* in_sizes, int n_in,
                              void* d_out, int out_size) {
    (void)in_sizes; (void)n_in; (void)out_size;
    const float* x     = (const float*)d_in[0];
    const float* gamma = (const float*)d_in[1];
    const float* beta  = (const float*)d_in[2];
    const float* wq    = (const float*)d_in[3];
    const float* bq    = (const float*)d_in[4];
    const float* wk    = (const float*)d_in[5];
    const float* bk    = (const float*)d_in[6];
    const float* wv    = (const float*)d_in[7];
    const float* bv    = (const float*)d_in[8];
    const float* wo    = (const float*)d_in[9];
    const float* bo    = (const float*)d_in[10];
    float* out = (float*)d_out;

    __nv_bfloat16 *hn, *W, *qT, *kb, *vT, *attn, *outT;
    float* scores;
    cudaGetSymbolAddress((void**)&hn,     g_hn);
    cudaGetSymbolAddress((void**)&W,      g_W);
    cudaGetSymbolAddress((void**)&qT,     g_qT);
    cudaGetSymbolAddress((void**)&kb,     g_k);
    cudaGetSymbolAddress((void**)&vT,     g_vT);
    cudaGetSymbolAddress((void**)&scores, g_scores);
    cudaGetSymbolAddress((void**)&attn,   g_attn);
    cudaGetSymbolAddress((void**)&outT,   g_outT);

    // raise dynamic-smem cap for every instantiation (idempotent, not an alloc)
    cudaFuncSetAttribute((const void*)gemm_kernel<false,1,true,false>,
                         cudaFuncAttributeMaxDynamicSharedMemorySize, SMEM_BYTES);
    cudaFuncSetAttribute((const void*)gemm_kernel<false,0,true,false>,
                         cudaFuncAttributeMaxDynamicSharedMemorySize, SMEM_BYTES);
    cudaFuncSetAttribute((const void*)gemm_kernel<false,2,false,false>,
                         cudaFuncAttributeMaxDynamicSharedMemorySize, SMEM_BYTES);
    cudaFuncSetAttribute((const void*)gemm_kernel<false,0,false,false>,
                         cudaFuncAttributeMaxDynamicSharedMemorySize, SMEM_BYTES);
    cudaFuncSetAttribute((const void*)gemm_kernel<true,2,true,true>,
                         cudaFuncAttributeMaxDynamicSharedMemorySize, SMEM_BYTES);

    gn_kernel<<<BATCH * NGRP, 256>>>(x, gamma, beta, hn);
    convw_kernel<<<4 * C_DIM * C_DIM / 256, 256>>>(wq, wk, wv, wo, W);

    const long long sHN = (long long)C_DIM * HW;   // 512*4096
    const long long sT  = (long long)HW * C_DIM;   // 4096*512
    const long long sSC = (long long)HW * HW;      // 4096*4096
    const float qscale = 0.044194173824159216f;    // 512^-0.5

    dim3 gProj(HW / BN, C_DIM / BM, BATCH);        // (32,4,2)
    // q^T = ((Wq hn + bq) * scale)^T   -> [b, hw, c]
    gemm_kernel<false,1,true,false><<<gProj,256,SMEM_BYTES>>>(W,            hn, qT, bq, nullptr,
        C_DIM, HW, C_DIM, C_DIM, HW, C_DIM, 0, sHN, sT, 0, qscale);
    // k = Wk hn + bk                    -> [b, c, hw]
    gemm_kernel<false,0,true,false><<<gProj,256,SMEM_BYTES>>>(W + 262144,   hn, kb, bk, nullptr,
        C_DIM, HW, C_DIM, C_DIM, HW, HW,    0, sHN, sHN, 0, 1.0f);
    // v^T = (Wv hn + bv)^T              -> [b, hw, c]
    gemm_kernel<false,1,true,false><<<gProj,256,SMEM_BYTES>>>(W + 2*262144, hn, vT, bv, nullptr,
        C_DIM, HW, C_DIM, C_DIM, HW, C_DIM, 0, sHN, sT, 0, 1.0f);

    // scores[i,j] = qT[i,:] . k[:,j]   (scale already folded into q)
    dim3 gScores(HW / BN, HW / BM, BATCH);         // (32,32,2)
    gemm_kernel<false,2,false,false><<<gScores,256,SMEM_BYTES>>>(qT, kb, scores, nullptr, nullptr,
        HW, HW, C_DIM, C_DIM, HW, HW, sT, sHN, sSC, 0, 1.0f);

    softmax_kernel<<<BATCH * HW, 256>>>(scores, attn);

    // outT[i,c] = attn[i,:] . vT[:,c]
    dim3 gOut(C_DIM / BN, HW / BM, BATCH);         // (4,32,2)
    gemm_kernel<false,0,false,false><<<gOut,256,SMEM_BYTES>>>(attn, vT, outT, nullptr, nullptr,
        HW, C_DIM, HW, HW, C_DIM, C_DIM, sSC, sT, sT, 0, 1.0f);

    // y = x + Wo out + bo   (out[i,p] = outT[p,i] -> B col-major, ldb = 512)
    gemm_kernel<true,2,true,true><<<gProj,256,SMEM_BYTES>>>(W + 3*262144, outT, out, bo, x,
        C_DIM, HW, C_DIM, C_DIM, C_DIM, HW, 0, sT, sHN, sHN, 1.0f);
}